// round 16
// baseline (speedup 1.0000x reference)
#include <cuda_runtime.h>
#include <cuda_bf16.h>

// AMSoftmaxLoss: score (2048 x 50257) fp32, labels (2048) int32 in {0,1}
// One 1024-thread block per row, occupancy 2/SM (64 warps): 296 slots ->
// 2048/296 = 6.92 waves = 98.8% sched utilization, and only 296 concurrent
// DRAM streams (4x fewer page conflicts). Inner loop: R11's proven 4-deep
// plain LDG.128. Fused last-arriving-block finale.

#define NROWS 2048
#define CCOLS 50257
#define BLK   1024

__device__ float g_rowL[NROWS];
__device__ unsigned int g_count = 0;   // self-resetting via atomicInc wrap

__device__ __forceinline__ float ex2f(float x) {
    float y;
    asm("ex2.approx.ftz.f32 %0, %1;" : "=f"(y) : "f"(x));
    return y;
}

#define SL2E (30.0f * 1.44269504088896340736f)   // S * log2(e)

__global__ __launch_bounds__(BLK, 2) void amsm_kernel(
    const float* __restrict__ score,
    const int* __restrict__ labels,
    float* __restrict__ out)
{
    const int row  = blockIdx.x;
    const int tid  = threadIdx.x;
    const int lane = tid & 31;
    const int wid  = tid >> 5;
    const float* __restrict__ p = score + (size_t)row * CCOLS;

    // Row base is (row mod 4) floats off 16B alignment (50257 % 4 == 1).
    const int peel = (4 - (row & 3)) & 3;

    float s0 = 0.f, s1 = 0.f, s2 = 0.f, s3 = 0.f;
    if (tid < peel) s0 += ex2f(SL2E * p[tid]);

    const int n4 = (CCOLS - peel) >> 2;
    const float4* __restrict__ q = (const float4*)(p + peel);

    int i = tid;
    // 4 x LDG.128 in flight per thread
    for (; i + 3 * BLK < n4; i += 4 * BLK) {
        float4 a = q[i];
        float4 b = q[i + BLK];
        float4 c = q[i + 2 * BLK];
        float4 d = q[i + 3 * BLK];
        s0 += ex2f(SL2E * a.x); s1 += ex2f(SL2E * a.y);
        s2 += ex2f(SL2E * a.z); s3 += ex2f(SL2E * a.w);
        s0 += ex2f(SL2E * b.x); s1 += ex2f(SL2E * b.y);
        s2 += ex2f(SL2E * b.z); s3 += ex2f(SL2E * b.w);
        s0 += ex2f(SL2E * c.x); s1 += ex2f(SL2E * c.y);
        s2 += ex2f(SL2E * c.z); s3 += ex2f(SL2E * c.w);
        s0 += ex2f(SL2E * d.x); s1 += ex2f(SL2E * d.y);
        s2 += ex2f(SL2E * d.z); s3 += ex2f(SL2E * d.w);
    }
    for (; i < n4; i += BLK) {
        float4 a = q[i];
        s0 += ex2f(SL2E * a.x); s1 += ex2f(SL2E * a.y);
        s2 += ex2f(SL2E * a.z); s3 += ex2f(SL2E * a.w);
    }
    const int tail = peel + 4 * n4;
    if (tid < CCOLS - tail) s0 += ex2f(SL2E * p[tail + tid]);

    float v = (s0 + s1) + (s2 + s3);

    // Block reduction: warp shuffle, then first warp folds 32 partials.
    __shared__ float wsum[BLK / 32];
    #pragma unroll
    for (int off = 16; off > 0; off >>= 1)
        v += __shfl_down_sync(0xFFFFFFFFu, v, off);
    if (lane == 0) wsum[wid] = v;
    __syncthreads();

    __shared__ unsigned s_last;
    if (tid < 32) {
        float w = wsum[tid];
        #pragma unroll
        for (int off = 16; off > 0; off >>= 1)
            w += __shfl_down_sync(0xFFFFFFFFu, w, off);
        if (tid == 0) {
            int lab = labels[row] & 1;             // 0 or 1
            float m = lab ? 0.4f : 0.1f;
            float t = p[lab];                      // target logit
            float num = 30.0f * (t - m);
            float excl = w - ex2f(SL2E * t);       // sum minus target term
            float denom = ex2f(num * 1.44269504088896340736f) + excl;
            g_rowL[row] = num - logf(denom);
            __threadfence();
            unsigned old = atomicInc(&g_count, NROWS - 1);  // wraps -> reset
            s_last = (old == NROWS - 1) ? 1u : 0u;
        }
    }
    __syncthreads();

    // Last-arriving block reduces all row losses and writes the output.
    if (s_last) {
        volatile float* rl = g_rowL;
        double acc = 0.0;
        for (int r = tid; r < NROWS; r += BLK)
            acc += (double)rl[r];
        __shared__ double dred[BLK];
        dred[tid] = acc;
        __syncthreads();
        #pragma unroll
        for (int off = BLK / 2; off > 0; off >>= 1) {
            if (tid < off) dred[tid] += dred[tid + off];
            __syncthreads();
        }
        if (tid == 0)
            out[0] = (float)(-dred[0] / (double)NROWS);
    }
}

extern "C" void kernel_launch(void* const* d_in, const int* in_sizes, int n_in,
                              void* d_out, int out_size)
{
    const float* score = (const float*)d_in[0];
    const int* labels = (const int*)d_in[1];
    float* out = (float*)d_out;

    amsm_kernel<<<NROWS, BLK>>>(score, labels, out);
}